// round 1
// baseline (speedup 1.0000x reference)
#include <cuda_runtime.h>
#include <cuda_bf16.h>
#include <math.h>

#define NV    6144
#define DV    65
#define HV    4
#define EPSV  1e-7f
#define MINV  1e-15f
#define NSEG  32
#define SEGR  192     // NV / NSEG
#define CAP   24      // max nonzeros per (col, segment); P(overflow) ~ 1e-24

// ---------------- scratch (device globals; no allocation at runtime) ----------------
__device__ int   g_cnt[NV * NSEG];
__device__ int   g_nbr[(size_t)NV * NSEG * CAP];
__device__ float g_att[(size_t)HV * NV * 65];
__device__ float g_pv [(size_t)HV * NV * 64];
__device__ float g_lam[(size_t)HV * NV];
__device__ float g_lm [(size_t)NV * 256];
__device__ float g_pre[(size_t)NV * 260];
__device__ float g_WaT[HV * 65 * 65];
__device__ float g_WdT[HV * 65 * 65];
__device__ float g_WoT[HV * 65 * 65];
__device__ float g_WlT[257 * 260];

// ---------------- helpers ----------------
__device__ __forceinline__ float wred(float v) {
#pragma unroll
    for (int o = 16; o; o >>= 1) v += __shfl_xor_sync(0xffffffffu, v, o);
    return v;  // deterministic fixed butterfly
}

__device__ __forceinline__ float acoshr(float z) {
    float t = fmaxf(z * z - 1.0f, 0.0f);
    return logf(z + sqrtf(t));
}

// block reduce, NW warps (blockDim = 32*NW), deterministic fixed order
template <int NW>
__device__ __forceinline__ float bredN(float v, float* s) {
    int t = threadIdx.x;
    __syncthreads();
    v = wred(v);
    if ((t & 31) == 0) s[t >> 5] = v;
    __syncthreads();
    float r = 0.0f;
#pragma unroll
    for (int w = 0; w < NW; w++) r += s[w];
    return r;
}

// ---------------- K0: weight transposes ----------------
__global__ void k_t65(const float* __restrict__ W, float* __restrict__ WT) {
    int idx = blockIdx.x * 256 + threadIdx.x;
    if (idx < HV * 65 * 65) {
        int m = idx / 4225, r = idx % 4225, k = r / 65, c = r % 65;
        WT[m * 4225 + c * 65 + k] = W[idx];
    }
}
__global__ void k_tlin(const float* __restrict__ W) {
    int idx = blockIdx.x * 256 + threadIdx.x;
    if (idx < 260 * 257) {
        int k = idx / 257, c = idx % 257;
        g_WlT[(size_t)c * 260 + k] = W[idx];
    }
}

// ---------------- K1: segmented neighbor-list build (deterministic, no atomics) ----
__global__ __launch_bounds__(256) void k_build(const float* __restrict__ adj) {
    int c   = blockIdx.x * 256 + threadIdx.x;   // column of adj = row of adj_t
    int seg = blockIdx.y;
    int cnt = 0;
    size_t base = ((size_t)c * NSEG + seg) * CAP;
    int j0 = seg * SEGR;
    for (int r = 0; r < SEGR; r += 8) {
        float v[8];
#pragma unroll
        for (int u = 0; u < 8; u++) v[u] = adj[(size_t)(j0 + r + u) * NV + c];
#pragma unroll
        for (int u = 0; u < 8; u++) {
            if (v[u] > 0.01f) {
                if (cnt < CAP) g_nbr[base + cnt] = j0 + r + u;
                cnt++;
            }
        }
    }
    g_cnt[c * NSEG + seg] = (cnt < CAP) ? cnt : CAP;
}

// ---------------- K2: att/red hyp_linear per node (warp-per-node) ----------------
__global__ __launch_bounds__(128) void k_feat(const float* __restrict__ x) {
    int w = threadIdx.x >> 5, l = threadIdx.x & 31;
    int i = blockIdx.x * 4 + w;
    __shared__ float su[4][64];
    const float* xr = x + (size_t)i * 65;
    float x0  = xr[0];
    float xv1 = xr[1 + l], xv2 = xr[33 + l];
    float ny  = fmaxf(sqrtf(wred(xv1 * xv1 + xv2 * xv2)), MINV);
    float ac  = acoshr(fmaxf(x0, 1.0f + EPSV));
    su[w][l]      = ac * xv1 / ny;
    su[w][l + 32] = ac * xv2 / ny;
    __syncwarp();
#pragma unroll
    for (int m = 0; m < 8; m++) {
        int h = m >> 1;
        const float* WT = ((m & 1) ? g_WdT : g_WaT) + h * 4225;
        float oa = 0.f, ob = 0.f, oc = 0.f;
#pragma unroll 8
        for (int c = 0; c < 64; c++) {
            float u = su[w][c];
            const float* col = WT + (c + 1) * 65;
            oa += u * col[l];
            ob += u * col[l + 32];
            oc += u * col[64];
        }
        float c1 = ((l > 0) ? oa * oa : 0.f) + ob * ob + ((l == 0) ? oc * oc : 0.f);
        float n2 = fmaxf(sqrtf(wred(c1)), MINV);
        float sh = sinhf(n2) / n2;
        float ya = sh * oa, yb = sh * ob, yc = sh * oc;
        float c2 = ((l > 0) ? ya * ya : 0.f) + yb * yb + ((l == 0) ? yc * yc : 0.f);
        float tv = sqrtf(1.0f + wred(c2));
        size_t base = (size_t)h * NV + i;
        if ((m & 1) == 0) {
            float* A = g_att + base * 65;
            A[l]      = (l == 0) ? tv : ya;
            A[l + 32] = yb;
            if (l == 0) A[64] = yc;
        } else {
            float tp1 = tv + 1.0f;
            float pva = ya / tp1, pvb = yb / tp1, pvc = yc / tp1;
            float* P = g_pv + base * 64;
            if (l > 0) P[l - 1] = pva;
            P[l + 31] = pvb;
            if (l == 0) P[63] = pvc;
            float c3 = ((l > 0) ? pva * pva : 0.f) + pvb * pvb + ((l == 0) ? pvc * pvc : 0.f);
            float s3 = wred(c3);
            if (l == 0) g_lam[base] = 2.0f / fmaxf(1.0f - s3, MINV);
        }
    }
}

// ---------------- K3: sparse attention + möbius + Wo + fused final logmap ----------
__global__ __launch_bounds__(128) void k_attn(void) {
    int i = blockIdx.x;
    int w = threadIdx.x >> 5, l = threadIdx.x & 31;
    int h = w;
    __shared__ float sp[256];
    __shared__ float wlm[4][64];
    __shared__ float sred[4];

    const float* Ai = g_att + ((size_t)h * NV + i) * 65;
    float ai0 = Ai[0], ai1 = Ai[1 + l], ai2 = Ai[33 + l];
    int cnt_l = g_cnt[i * NSEG + l];

    float T1 = 0.f, T2 = 0.f, U = 0.f, Q = 0.f;
    for (int seg = 0; seg < NSEG; seg++) {
        int cnt = __shfl_sync(0xffffffffu, cnt_l, seg);
        const int* lst = g_nbr + ((size_t)i * NSEG + seg) * CAP;
        for (int k = 0; k < cnt; k++) {
            int j = lst[k];
            const float* Aj = g_att + ((size_t)h * NV + j) * 65;
            float aj0 = Aj[0];
            float d = ((l == 0) ? ai0 * aj0 : 0.f) - ai1 * Aj[1 + l] - ai2 * Aj[33 + l];
            d = wred(d);
            float th = fmaxf(d, 1.0f + EPSV);
            float ar = acoshr(th);
            float S  = fminf(ar * ar, 50.0f);
            float lamj = g_lam[(size_t)h * NV + j];
            const float* Pj = g_pv + ((size_t)h * NV + j) * 64;
            float sl = S * lamj;
            T1 += sl * Pj[l];
            T2 += sl * Pj[l + 32];
            U  += S * (lamj - 1.0f);
            Q  += S * S;
        }
    }
    float nrm = fmaxf(sqrtf(Q), 1e-12f);
    float den = fmaxf(U / nrm, MINV);
    float v1 = (-T1 / nrm) / den, v2 = (-T2 / nrm) / den;
    float nv = fmaxf(sqrtf(wred(v1 * v1 + v2 * v2)), MINV);
    float ncl = fminf(nv, 1.0f - EPSV);
    float f = tanhf(0.5f * atanhf(ncl)) / nv;
    float m1 = f * v1, m2 = f * v2;
    float s2 = wred(m1 * m1 + m2 * m2);
    float dd = fmaxf(1.0f - s2, MINV);
    float hb0 = (1.0f + s2) / dd;
    float y1 = 2.0f * m1 / dd, y2 = 2.0f * m2 / dd;
    float nyy = fmaxf(sqrtf(wred(y1 * y1 + y2 * y2)), MINV);
    float acl = acoshr(fmaxf(hb0, 1.0f + EPSV));
    wlm[w][l]      = acl * y1 / nyy;
    wlm[w][l + 32] = acl * y2 / nyy;
    __syncwarp();

    const float* WT = g_WoT + h * 4225;
    float oa = 0.f, ob = 0.f, oc = 0.f;
#pragma unroll 8
    for (int c = 0; c < 64; c++) {
        float u = wlm[w][c];
        const float* col = WT + (c + 1) * 65;
        oa += u * col[l];
        ob += u * col[l + 32];
        oc += u * col[64];
    }
    float c1 = ((l > 0) ? oa * oa : 0.f) + ob * ob + ((l == 0) ? oc * oc : 0.f);
    float n2 = fmaxf(sqrtf(wred(c1)), MINV);
    float sh = sinhf(n2) / n2;
    float ya = sh * oa, yb = sh * ob, yc = sh * oc;
    float c2 = ((l > 0) ? ya * ya : 0.f) + yb * yb + ((l == 0) ? yc * yc : 0.f);
    float tv = sqrtf(1.0f + wred(c2));
    float tp1 = tv + 1.0f;
    if (l > 0) sp[h * 64 + l - 1] = ya / tp1;
    sp[h * 64 + l + 31] = yb / tp1;
    if (l == 0) sp[h * 64 + 63] = yc / tp1;
    __syncthreads();

    // fused final to_hyperboloid + logmap0 over concatenated p (256 dims)
    int t = threadIdx.x;
    float pa = sp[t], pb = sp[t + 128];
    float ssum = bredN<4>(pa * pa + pb * pb, sred);
    float ddf = fmaxf(1.0f - ssum, MINV);
    float h0 = (1.0f + ssum) / ddf;
    float ya2 = 2.0f * pa / ddf, yb2 = 2.0f * pb / ddf;
    float ny2 = bredN<4>(ya2 * ya2 + yb2 * yb2, sred);
    float nyf = fmaxf(sqrtf(ny2), MINV);
    float acf = acoshr(fmaxf(h0, 1.0f + EPSV));
    g_lm[(size_t)i * 256 + t]       = acf * ya2 / nyf;
    g_lm[(size_t)i * 256 + t + 128] = acf * yb2 / nyf;
}

// ---------------- K4: tiled GEMM  (6144x256) @ (256x260) -> g_pre ----------------
__global__ __launch_bounds__(260) void k_lin(void) {
    __shared__ float ws[32 * 260];
    __shared__ float lms[16][33];
    int t = threadIdx.x;
    int i0 = blockIdx.x * 16;
    float acc[16];
#pragma unroll
    for (int g = 0; g < 16; g++) acc[g] = 0.f;

    for (int c0 = 0; c0 < 256; c0 += 32) {
        __syncthreads();
        for (int idx = t; idx < 512; idx += 260) {
            int g = idx >> 5, cc = idx & 31;
            lms[g][cc] = g_lm[(size_t)(i0 + g) * 256 + c0 + cc];
        }
#pragma unroll
        for (int cc = 0; cc < 32; cc++)
            ws[cc * 260 + t] = g_WlT[(size_t)(c0 + cc + 1) * 260 + t];
        __syncthreads();
#pragma unroll
        for (int cc = 0; cc < 32; cc++) {
            float wv = ws[cc * 260 + t];
#pragma unroll
            for (int g = 0; g < 16; g++) acc[g] += lms[g][cc] * wv;
        }
    }
#pragma unroll
    for (int g = 0; g < 16; g++) g_pre[(size_t)(i0 + g) * 260 + t] = acc[g];
}

// ---------------- K5: final expmap0 + hyp_proj epilogue ----------------
__global__ __launch_bounds__(256) void k_final(float* __restrict__ out) {
    int i = blockIdx.x, t = threadIdx.x;
    __shared__ float sred[8];
    float v0 = g_pre[(size_t)i * 260 + t];
    float v1 = 0.f;
    if (t < 4) v1 = g_pre[(size_t)i * 260 + 256 + t];
    float c = ((t > 0) ? v0 * v0 : 0.f) + ((t < 4) ? v1 * v1 : 0.f);
    float n2sq = bredN<8>(c, sred);
    float n2 = fmaxf(sqrtf(n2sq), MINV);
    float sh = sinhf(n2) / n2;
    float y0 = sh * v0, y1 = sh * v1;
    float c2 = ((t > 0) ? y0 * y0 : 0.f) + ((t < 4) ? y1 * y1 : 0.f);
    float sy = bredN<8>(c2, sred);
    float tv = sqrtf(1.0f + sy);
    out[(size_t)i * 260 + t] = (t == 0) ? tv : y0;
    if (t < 4) out[(size_t)i * 260 + 256 + t] = y1;
}

// ---------------- launch ----------------
extern "C" void kernel_launch(void* const* d_in, const int* in_sizes, int n_in,
                              void* d_out, int out_size) {
    const float* x     = (const float*)d_in[0];
    const float* adj   = (const float*)d_in[1];
    const float* W_att = (const float*)d_in[2];
    const float* W_dat = (const float*)d_in[3];
    const float* W_out = (const float*)d_in[4];
    const float* W_lin = (const float*)d_in[5];
    float* out = (float*)d_out;

    float *waT, *wdT, *woT;
    cudaGetSymbolAddress((void**)&waT, g_WaT);
    cudaGetSymbolAddress((void**)&wdT, g_WdT);
    cudaGetSymbolAddress((void**)&woT, g_WoT);

    k_t65<<<(HV * 65 * 65 + 255) / 256, 256>>>(W_att, waT);
    k_t65<<<(HV * 65 * 65 + 255) / 256, 256>>>(W_dat, wdT);
    k_t65<<<(HV * 65 * 65 + 255) / 256, 256>>>(W_out, woT);
    k_tlin<<<(260 * 257 + 255) / 256, 256>>>(W_lin);

    k_build<<<dim3(NV / 256, NSEG), 256>>>(adj);
    k_feat<<<NV / 4, 128>>>(x);
    k_attn<<<NV, 128>>>();
    k_lin<<<NV / 16, 260>>>();
    k_final<<<NV, 256>>>(out);
}

// round 2
// speedup vs baseline: 1.4314x; 1.4314x over previous
#include <cuda_runtime.h>
#include <cuda_bf16.h>
#include <math.h>

#define NV    6144
#define HV    4
#define EPSV  1e-7f
#define MINV  1e-15f
#define NSEG  32
#define SEGR  192
#define CAP   24
#define AST   68     // padded row stride for att/pv (16B-aligned rows)

// ---------------- scratch ----------------
__device__ int   g_cnt[NV * NSEG];
__device__ int   g_nbr[(size_t)NV * NSEG * CAP];
__device__ float g_att[(size_t)HV * NV * AST];   // [0..63]=y, [64]=t
__device__ float g_pv [(size_t)HV * NV * AST];   // [0..63]=pv, [64]=lambda
__device__ float g_lm [(size_t)NV * 256];
__device__ float g_WoT[HV * 65 * 65];
__device__ float g_WlT[257 * 260];

// ---------------- helpers ----------------
__device__ __forceinline__ float wred(float v) {
#pragma unroll
    for (int o = 16; o; o >>= 1) v += __shfl_xor_sync(0xffffffffu, v, o);
    return v;
}
__device__ __forceinline__ float acoshr(float z) {
    float t = fmaxf(z * z - 1.0f, 0.0f);
    return logf(z + sqrtf(t));
}

// ---------------- K1: neighbor lists + W_lin transpose (fused) ----------------
__global__ __launch_bounds__(256) void k_build(const float* __restrict__ adj,
                                               const float* __restrict__ Wl) {
    if (blockIdx.y == NSEG) {  // W_lin transpose
        for (int e = blockIdx.x * 256 + threadIdx.x; e < 260 * 257; e += 24 * 256) {
            int k = e / 257, c = e % 257;
            g_WlT[(size_t)c * 260 + k] = Wl[e];
        }
        return;
    }
    int c   = blockIdx.x * 256 + threadIdx.x;
    int seg = blockIdx.y;
    int cnt = 0;
    size_t base = ((size_t)c * NSEG + seg) * CAP;
    int j0 = seg * SEGR;
    for (int r = 0; r < SEGR; r += 8) {
        float v[8];
#pragma unroll
        for (int u = 0; u < 8; u++) v[u] = adj[(size_t)(j0 + r + u) * NV + c];
#pragma unroll
        for (int u = 0; u < 8; u++) {
            if (v[u] > 0.01f) {
                if (cnt < CAP) g_nbr[base + cnt] = j0 + r + u;
                cnt++;
            }
        }
    }
    g_cnt[c * NSEG + seg] = (cnt < CAP) ? cnt : CAP;
}

// ---------------- K2: hyp_linear for att/data, node-per-lane ----------------
// grid (48, 8): by = matrix (0..3 att heads, 4..7 data heads); block 128 thr.
// smem: su[128*65] | sW4[65*16 float4] | sout[4][65*33] | stats[3*128]
#define SU_OFF  0
#define SW_OFF  8320
#define SO_OFF  12480
#define ST_OFF  21060
#define SMEM_FEAT ((21060 + 384) * 4)

__global__ __launch_bounds__(128) void k_feat(const float* __restrict__ x,
                                              const float* __restrict__ Wa,
                                              const float* __restrict__ Wd,
                                              const float* __restrict__ Wo) {
    extern __shared__ float sm[];
    float*  su  = sm + SU_OFF;
    float*  sW  = sm + SW_OFF;
    float4* sW4 = (float4*)sW;
    float*  st  = sm + ST_OFF;
    int t = threadIdx.x, w = t >> 5, l = t & 31;
    int m = blockIdx.y, h = m & 3;
    const float* W = (m < 4) ? (Wa + h * 4225) : (Wd + h * 4225);
    int nb = blockIdx.x * 128;

    // side job: transpose W_out (for k_attn epilogue)
    if (m == 0) {
        for (int e = blockIdx.x * 128 + t; e < HV * 65 * 65; e += 48 * 128) {
            int hh = e / 4225, r = e % 4225, o = r / 65, c = r % 65;
            g_WoT[hh * 4225 + c * 65 + o] = Wo[e];
        }
    }

    for (int e = t; e < 128 * 65; e += 128) su[e] = x[(size_t)nb * 65 + e];
    for (int e = t; e < 65 * 64; e += 128) {
        int o = e >> 6, c = e & 63;
        sW[e] = W[o * 65 + 1 + c];
    }
    __syncthreads();

    // per-lane node: logmap0 into registers
    int ln = w * 32 + l;
    float u[64];
    float x0 = su[ln * 65];
    float q0 = 0.f, q1 = 0.f, q2 = 0.f, q3 = 0.f;
#pragma unroll
    for (int c = 0; c < 64; c += 4) {
        float a = su[ln * 65 + 1 + c], b = su[ln * 65 + 2 + c];
        float cc = su[ln * 65 + 3 + c], d = su[ln * 65 + 4 + c];
        u[c] = a; u[c + 1] = b; u[c + 2] = cc; u[c + 3] = d;
        q0 += a * a; q1 += b * b; q2 += cc * cc; q3 += d * d;
    }
    float nsq = (q0 + q1) + (q2 + q3);
    float ny = fmaxf(sqrtf(nsq), MINV);
    float scale = acoshr(fmaxf(x0, 1.0f + EPSV)) / ny;
#pragma unroll
    for (int c = 0; c < 64; c++) u[c] *= scale;

    // matvec (o outer, weights broadcast from smem)
    float* so = sm + SO_OFF + w * 2145;
    float osq = 0.f;
    for (int o = 0; o < 65; o++) {
        float a0 = 0.f, a1 = 0.f, a2 = 0.f, a3 = 0.f;
#pragma unroll
        for (int c4 = 0; c4 < 16; c4++) {
            float4 wv = sW4[o * 16 + c4];
            a0 += wv.x * u[4 * c4];
            a1 += wv.y * u[4 * c4 + 1];
            a2 += wv.z * u[4 * c4 + 2];
            a3 += wv.w * u[4 * c4 + 3];
        }
        float ov = (a0 + a1) + (a2 + a3);
        so[o * 33 + l] = ov;
        if (o >= 1) osq += ov * ov;
    }

    float n2 = fmaxf(sqrtf(osq), MINV);
    float shv = sinhf(n2) / n2;
    float ysq = shv * shv * osq;
    float tv = sqrtf(1.0f + ysq);
    st[t] = shv; st[128 + t] = tv;
    if (m >= 4) {
        float tp1 = tv + 1.0f;
        float pvsq = ysq / (tp1 * tp1);
        st[256 + t] = 2.0f / fmaxf(1.0f - pvsq, MINV);
    }
    __syncwarp();

    // transpose-write, coalesced per node
    float* dst = (m < 4) ? g_att : g_pv;
    for (int n = 0; n < 32; n++) {
        int nd = nb + w * 32 + n;
        float* R = dst + ((size_t)(h * NV) + nd) * AST;
        float shn = st[w * 32 + n];
        float y1 = shn * so[(l + 1) * 33 + n];
        float y2 = shn * so[(l + 33) * 33 + n];
        if (m < 4) {
            R[l] = y1; R[l + 32] = y2;
            if (l == 0) R[64] = st[128 + w * 32 + n];
        } else {
            float inv = 1.0f / (st[128 + w * 32 + n] + 1.0f);
            R[l] = y1 * inv; R[l + 32] = y2 * inv;
            if (l == 0) R[64] = st[256 + w * 32 + n];
        }
    }
}

// ---------------- K3: sparse attention, 4 neighbors/warp ----------------
__global__ __launch_bounds__(128) void k_attn(void) {
    int i = blockIdx.x;
    int w = threadIdx.x >> 5, l = threadIdx.x & 31;
    int h = w;
    int s = l & 7, g = l >> 3;
    __shared__ int slist[800];
    __shared__ int stot;
    __shared__ float sp[256];
    __shared__ float wlm[4][64];
    __shared__ float sred[4];

    if (threadIdx.x < 32) {
        int c = g_cnt[i * NSEG + l];
        int sc = c;
#pragma unroll
        for (int o = 1; o < 32; o <<= 1) {
            int v = __shfl_up_sync(0xffffffffu, sc, o);
            if (l >= o) sc += v;
        }
        int off = sc - c;
        const int* lst = g_nbr + ((size_t)i * NSEG + l) * CAP;
        for (int k = 0; k < c; k++) slist[off + k] = lst[k];
        if (l == 31) stot = sc;
    }
    __syncthreads();
    int nk = stot;
    int nk4 = (nk + 3) & ~3;
    if (threadIdx.x < nk4 - nk) slist[nk + threadIdx.x] = slist[0];
    __syncthreads();

    const float* Ai = g_att + ((size_t)(h * NV) + i) * AST;
    float4 a0 = *(const float4*)(Ai + 8 * s);
    float4 a1 = *(const float4*)(Ai + 8 * s + 4);
    float ai0 = Ai[64];

    float T1 = 0.f, T2 = 0.f, U = 0.f, Q = 0.f;
    for (int kc = 0; kc < nk4; kc += 4) {
        int j = slist[kc + g];
        const float* Aj = g_att + ((size_t)(h * NV) + j) * AST;
        float4 b0 = *(const float4*)(Aj + 8 * s);
        float4 b1 = *(const float4*)(Aj + 8 * s + 4);
        float aj0 = Aj[64];
        float part = a0.x * b0.x + a0.y * b0.y + a0.z * b0.z + a0.w * b0.w
                   + a1.x * b1.x + a1.y * b1.y + a1.z * b1.z + a1.w * b1.w;
#pragma unroll
        for (int o = 4; o; o >>= 1) part += __shfl_xor_sync(0xffffffffu, part, o);
        float th = fmaxf(ai0 * aj0 - part, 1.0f + EPSV);
        float ar = acoshr(th);
        float S = fminf(ar * ar, 50.0f);
        if (kc + g >= nk) S = 0.0f;
#pragma unroll
        for (int gg = 0; gg < 4; gg++) {
            float Sg = __shfl_sync(0xffffffffu, S, gg * 8 + s);
            int jg = slist[kc + gg];
            const float* Pj = g_pv + ((size_t)(h * NV) + jg) * AST;
            float lam = Pj[64];
            float slg = Sg * lam;
            T1 += slg * Pj[l];
            T2 += slg * Pj[l + 32];
            U  += Sg * (lam - 1.0f);
            Q  += Sg * Sg;
        }
    }

    float nrm = fmaxf(sqrtf(Q), 1e-12f);
    float den = fmaxf(U / nrm, MINV);
    float v1 = (-T1 / nrm) / den, v2 = (-T2 / nrm) / den;
    float nv = fmaxf(sqrtf(wred(v1 * v1 + v2 * v2)), MINV);
    float ncl = fminf(nv, 1.0f - EPSV);
    float f = tanhf(0.5f * atanhf(ncl)) / nv;
    float m1 = f * v1, m2 = f * v2;
    float s2 = wred(m1 * m1 + m2 * m2);
    float dd = fmaxf(1.0f - s2, MINV);
    float hb0 = (1.0f + s2) / dd;
    float y1 = 2.0f * m1 / dd, y2 = 2.0f * m2 / dd;
    float nyy = fmaxf(sqrtf(wred(y1 * y1 + y2 * y2)), MINV);
    float acl = acoshr(fmaxf(hb0, 1.0f + EPSV));
    wlm[w][l]      = acl * y1 / nyy;
    wlm[w][l + 32] = acl * y2 / nyy;
    __syncwarp();

    // Wo matvec (warp, lane covers outputs l, l+32, 64)
    const float* WT = g_WoT + h * 4225;
    float oa = 0.f, ob = 0.f, oc = 0.f;
#pragma unroll 8
    for (int c = 0; c < 64; c++) {
        float uv = wlm[w][c];
        const float* col = WT + (c + 1) * 65;
        oa += uv * col[l];
        ob += uv * col[l + 32];
        oc += uv * col[64];
    }
    float c1 = ((l > 0) ? oa * oa : 0.f) + ob * ob + ((l == 0) ? oc * oc : 0.f);
    float n2 = fmaxf(sqrtf(wred(c1)), MINV);
    float sh = sinhf(n2) / n2;
    float ya = sh * oa, yb = sh * ob, yc = sh * oc;
    float c2 = ((l > 0) ? ya * ya : 0.f) + yb * yb + ((l == 0) ? yc * yc : 0.f);
    float tv = sqrtf(1.0f + wred(c2));
    float tp1 = tv + 1.0f;
    if (l > 0) sp[h * 64 + l - 1] = ya / tp1;
    sp[h * 64 + l + 31] = yb / tp1;
    if (l == 0) sp[h * 64 + 63] = yc / tp1;
    __syncthreads();

    // fused to_hyperboloid + logmap0 over concatenated 256-d p
    int t = threadIdx.x;
    float pa = sp[t], pb = sp[t + 128];
    float v = pa * pa + pb * pb;
    __syncthreads();
    v = wred(v);
    if ((t & 31) == 0) sred[t >> 5] = v;
    __syncthreads();
    float ssum = sred[0] + sred[1] + sred[2] + sred[3];
    float ddf = fmaxf(1.0f - ssum, MINV);
    float h0 = (1.0f + ssum) / ddf;
    float ya2 = 2.0f * pa / ddf, yb2 = 2.0f * pb / ddf;
    float ny2v = ya2 * ya2 + yb2 * yb2;
    __syncthreads();
    ny2v = wred(ny2v);
    if ((t & 31) == 0) sred[t >> 5] = ny2v;
    __syncthreads();
    float ny2 = sred[0] + sred[1] + sred[2] + sred[3];
    float nyf = fmaxf(sqrtf(ny2), MINV);
    float acf = acoshr(fmaxf(h0, 1.0f + EPSV));
    g_lm[(size_t)i * 256 + t]       = acf * ya2 / nyf;
    g_lm[(size_t)i * 256 + t + 128] = acf * yb2 / nyf;
}

// ---------------- K4: GEMM (6144x256)@(256x260) + fused final expmap ----------
__global__ __launch_bounds__(260) void k_linf(float* __restrict__ out) {
    __shared__ float ws[32 * 260];
    __shared__ float lms[16][33];
    __shared__ float sacc[16][261];
    int t = threadIdx.x;
    int i0 = blockIdx.x * 16;
    float acc[16];
#pragma unroll
    for (int g = 0; g < 16; g++) acc[g] = 0.f;

    for (int c0 = 0; c0 < 256; c0 += 32) {
        __syncthreads();
        for (int idx = t; idx < 512; idx += 260) {
            int g = idx >> 5, cc = idx & 31;
            lms[g][cc] = g_lm[(size_t)(i0 + g) * 256 + c0 + cc];
        }
#pragma unroll
        for (int cc = 0; cc < 32; cc++)
            ws[cc * 260 + t] = g_WlT[(size_t)(c0 + cc + 1) * 260 + t];
        __syncthreads();
#pragma unroll
        for (int cc = 0; cc < 32; cc++) {
            float wv = ws[cc * 260 + t];
#pragma unroll
            for (int g = 0; g < 16; g++) acc[g] += lms[g][cc] * wv;
        }
    }
    __syncthreads();
#pragma unroll
    for (int g = 0; g < 16; g++) sacc[g][t] = acc[g];
    __syncthreads();

    if (t < 256) {
        int g = t >> 4, m = t & 15;
        float q = 0.f;
        for (int d = m; d < 260; d += 16)
            if (d >= 1) { float vv = sacc[g][d]; q += vv * vv; }
#pragma unroll
        for (int o = 8; o; o >>= 1) q += __shfl_xor_sync(0xffffffffu, q, o);
        float n2 = fmaxf(sqrtf(q), MINV);
        float sh = sinhf(n2) / n2;
        float tv = sqrtf(1.0f + sh * sh * q);
        for (int d = m; d < 260; d += 16) {
            float vv = (d == 0) ? tv : sh * sacc[g][d];
            out[(size_t)(i0 + g) * 260 + d] = vv;
        }
    }
}

// ---------------- launch ----------------
extern "C" void kernel_launch(void* const* d_in, const int* in_sizes, int n_in,
                              void* d_out, int out_size) {
    const float* x     = (const float*)d_in[0];
    const float* adj   = (const float*)d_in[1];
    const float* W_att = (const float*)d_in[2];
    const float* W_dat = (const float*)d_in[3];
    const float* W_out = (const float*)d_in[4];
    const float* W_lin = (const float*)d_in[5];
    float* out = (float*)d_out;

    cudaFuncSetAttribute(k_feat, cudaFuncAttributeMaxDynamicSharedMemorySize, SMEM_FEAT);

    k_build<<<dim3(NV / 256, NSEG + 1), 256>>>(adj, W_lin);
    k_feat<<<dim3(NV / 128, 8), 128, SMEM_FEAT>>>(x, W_att, W_dat, W_out);
    k_attn<<<NV, 128>>>();
    k_linf<<<NV / 16, 260>>>(out);
}

// round 3
// speedup vs baseline: 1.5535x; 1.0853x over previous
#include <cuda_runtime.h>
#include <cuda_bf16.h>
#include <math.h>

#define NV    6144
#define HV    4
#define EPSV  1e-7f
#define MINV  1e-15f
#define NSEG  32
#define SEGR  192
#define CAP   24
#define AST   68
#define WLN   320

// ---------------- scratch (zero-init guarantees padding stays zero) ----------------
__device__ int   g_cnt[NV * NSEG];
__device__ int   g_nbr[(size_t)NV * NSEG * CAP];
__device__ float g_att[(size_t)HV * NV * AST];   // [0..63]=y, [64]=t
__device__ float g_pv [(size_t)HV * NV * AST];   // [0..63]=pv, [64]=lambda
__device__ float g_u  [(size_t)HV * NV * 64];    // per-head logmap vectors
__device__ float g_pc [(size_t)NV * 256];        // concatenated poincare
__device__ float g_s  [NV];                      // per-row logmap scalar
__device__ float g_pre[(size_t)NV * WLN];        // GEMM out (padded)
__device__ float g_WlP[256 * WLN];               // W_lin^T padded (cols>=260 zero)

// ---------------- helpers ----------------
__device__ __forceinline__ float wred(float v) {
#pragma unroll
    for (int o = 16; o; o >>= 1) v += __shfl_xor_sync(0xffffffffu, v, o);
    return v;
}
__device__ __forceinline__ float acoshr(float z) {
    float t = fmaxf(z * z - 1.0f, 0.0f);
    return logf(z + sqrtf(t));
}

// ---------------- K1: neighbor lists + W_lin transpose (fused) ----------------
__global__ __launch_bounds__(256) void k_build(const float* __restrict__ adj,
                                               const float* __restrict__ Wl) {
    if (blockIdx.y == NSEG) {
        for (int e = blockIdx.x * 256 + threadIdx.x; e < 256 * 260; e += 24 * 256) {
            int kk = e / 260, n = e % 260;
            g_WlP[(size_t)kk * WLN + n] = Wl[n * 257 + kk + 1];
        }
        return;
    }
    int c   = blockIdx.x * 256 + threadIdx.x;
    int seg = blockIdx.y;
    int cnt = 0;
    size_t base = ((size_t)c * NSEG + seg) * CAP;
    int j0 = seg * SEGR;
    for (int r = 0; r < SEGR; r += 8) {
        float v[8];
#pragma unroll
        for (int u = 0; u < 8; u++) v[u] = adj[(size_t)(j0 + r + u) * NV + c];
#pragma unroll
        for (int u = 0; u < 8; u++) {
            if (v[u] > 0.01f) {
                if (cnt < CAP) g_nbr[base + cnt] = j0 + r + u;
                cnt++;
            }
        }
    }
    g_cnt[c * NSEG + seg] = (cnt < CAP) ? cnt : CAP;
}

// ---------------- K2: hyp_linear att/data, node-per-lane ----------------
// grid (48, 8): by = matrix (0..3 att, 4..7 data); block 128.
#define SU_OFF  0                       // 128*65 = 8320
#define SW_OFF  8320                    // 64*64  = 4096
#define SO_OFF  12416                   // 4*64*33= 8448
#define ST_OFF  20864                   // 384
#define SMEM_FEAT ((20864 + 384) * 4)

__global__ __launch_bounds__(128) void k_feat(const float* __restrict__ x,
                                              const float* __restrict__ Wa,
                                              const float* __restrict__ Wd) {
    extern __shared__ float sm[];
    float*  su  = sm + SU_OFF;
    float*  sW  = sm + SW_OFF;
    float4* sW4 = (float4*)sW;
    float*  st  = sm + ST_OFF;
    int t = threadIdx.x, w = t >> 5, l = t & 31;
    int m = blockIdx.y, h = m & 3;
    const float* W = (m < 4) ? (Wa + h * 4225) : (Wd + h * 4225);
    int nb = blockIdx.x * 128;

    for (int e = t; e < 128 * 65; e += 128) su[e] = x[(size_t)nb * 65 + e];
    for (int e = t; e < 64 * 64; e += 128) {
        int oo = e >> 6, c = e & 63;
        sW[e] = W[(oo + 1) * 65 + 1 + c];   // rows 1..64, cols 1..64
    }
    __syncthreads();

    int ln = w * 32 + l;
    float u[64];
    float x0 = su[ln * 65];
    float q0 = 0.f, q1 = 0.f, q2 = 0.f, q3 = 0.f;
#pragma unroll
    for (int c = 0; c < 64; c += 4) {
        float a = su[ln * 65 + 1 + c], b = su[ln * 65 + 2 + c];
        float cc = su[ln * 65 + 3 + c], d = su[ln * 65 + 4 + c];
        u[c] = a; u[c + 1] = b; u[c + 2] = cc; u[c + 3] = d;
        q0 += a * a; q1 += b * b; q2 += cc * cc; q3 += d * d;
    }
    float nsq = (q0 + q1) + (q2 + q3);
    float ny = fmaxf(sqrtf(nsq), MINV);
    float scale = acoshr(fmaxf(x0, 1.0f + EPSV)) / ny;
#pragma unroll
    for (int c = 0; c < 64; c++) u[c] *= scale;

    float* so = sm + SO_OFF + w * 2112;
    float osq = 0.f;
    for (int oo = 0; oo < 64; oo++) {
        float a0 = 0.f, a1 = 0.f, a2 = 0.f, a3 = 0.f;
#pragma unroll
        for (int c4 = 0; c4 < 16; c4++) {
            float4 wv = sW4[oo * 16 + c4];
            a0 += wv.x * u[4 * c4];
            a1 += wv.y * u[4 * c4 + 1];
            a2 += wv.z * u[4 * c4 + 2];
            a3 += wv.w * u[4 * c4 + 3];
        }
        float ov = (a0 + a1) + (a2 + a3);
        so[oo * 33 + l] = ov;
        osq += ov * ov;
    }

    float n2 = fmaxf(sqrtf(osq), MINV);
    float shv = sinhf(n2) / n2;
    float ysq = shv * shv * osq;
    float tv = sqrtf(1.0f + ysq);
    st[t] = shv; st[128 + t] = tv;
    if (m >= 4) {
        float tp1 = tv + 1.0f;
        float pvsq = ysq / (tp1 * tp1);
        st[256 + t] = 2.0f / fmaxf(1.0f - pvsq, MINV);
    }
    __syncwarp();

    float* dst = (m < 4) ? g_att : g_pv;
    for (int n = 0; n < 32; n++) {
        int nd = nb + w * 32 + n;
        float* R = dst + ((size_t)(h * NV) + nd) * AST;
        float shn = st[w * 32 + n];
        float y1 = shn * so[l * 33 + n];
        float y2 = shn * so[(l + 32) * 33 + n];
        if (m < 4) {
            R[l] = y1; R[l + 32] = y2;
            if (l == 0) R[64] = st[128 + w * 32 + n];
        } else {
            float inv = 1.0f / (st[128 + w * 32 + n] + 1.0f);
            R[l] = y1 * inv; R[l + 32] = y2 * inv;
            if (l == 0) R[64] = st[256 + w * 32 + n];
        }
    }
}

// ---------------- K3: sparse attention + mobius -> g_u ----------------
__global__ __launch_bounds__(128) void k_attn(void) {
    int i = blockIdx.x;
    int w = threadIdx.x >> 5, l = threadIdx.x & 31;
    int h = w;
    int s = l & 7, g = l >> 3;
    __shared__ int slist[800];
    __shared__ int stot;

    if (threadIdx.x < 32) {
        int c = g_cnt[i * NSEG + l];
        int sc = c;
#pragma unroll
        for (int o = 1; o < 32; o <<= 1) {
            int v = __shfl_up_sync(0xffffffffu, sc, o);
            if (l >= o) sc += v;
        }
        int off = sc - c;
        const int* lst = g_nbr + ((size_t)i * NSEG + l) * CAP;
        for (int k = 0; k < c; k++) slist[off + k] = lst[k];
        if (l == 31) stot = sc;
    }
    __syncthreads();
    int nk = stot;
    int nk4 = (nk + 3) & ~3;
    if (threadIdx.x < nk4 - nk) slist[nk + threadIdx.x] = slist[0];
    __syncthreads();

    const float* Ai = g_att + ((size_t)(h * NV) + i) * AST;
    float4 a0 = *(const float4*)(Ai + 8 * s);
    float4 a1 = *(const float4*)(Ai + 8 * s + 4);
    float ai0 = Ai[64];

    float T1 = 0.f, T2 = 0.f, U = 0.f, Q = 0.f;
    for (int kc = 0; kc < nk4; kc += 4) {
        int j = slist[kc + g];
        const float* Aj = g_att + ((size_t)(h * NV) + j) * AST;
        float4 b0 = *(const float4*)(Aj + 8 * s);
        float4 b1 = *(const float4*)(Aj + 8 * s + 4);
        float aj0 = Aj[64];
        float part = a0.x * b0.x + a0.y * b0.y + a0.z * b0.z + a0.w * b0.w
                   + a1.x * b1.x + a1.y * b1.y + a1.z * b1.z + a1.w * b1.w;
#pragma unroll
        for (int o = 4; o; o >>= 1) part += __shfl_xor_sync(0xffffffffu, part, o);
        float th = fmaxf(ai0 * aj0 - part, 1.0f + EPSV);
        float ar = acoshr(th);
        float S = fminf(ar * ar, 50.0f);
        if (kc + g >= nk) S = 0.0f;
#pragma unroll
        for (int gg = 0; gg < 4; gg++) {
            float Sg = __shfl_sync(0xffffffffu, S, gg * 8 + s);
            int jg = slist[kc + gg];
            const float* Pj = g_pv + ((size_t)(h * NV) + jg) * AST;
            float lam = Pj[64];
            float slg = Sg * lam;
            T1 += slg * Pj[l];
            T2 += slg * Pj[l + 32];
            U  += Sg * (lam - 1.0f);
            Q  += Sg * Sg;
        }
    }

    float nrm = fmaxf(sqrtf(Q), 1e-12f);
    float den = fmaxf(U / nrm, MINV);
    float v1 = (-T1 / nrm) / den, v2 = (-T2 / nrm) / den;
    float nvsq = wred(v1 * v1 + v2 * v2);
    float nv = fmaxf(sqrtf(nvsq), MINV);
    float ncl = fminf(nv, 1.0f - EPSV);
    float f = tanhf(0.5f * atanhf(ncl)) / nv;
    float m1 = f * v1, m2 = f * v2;
    float s2 = f * f * nvsq;                       // = sum(m^2)
    float dd = fmaxf(1.0f - s2, MINV);
    float hb0 = (1.0f + s2) / dd;
    // logmap0(to_hyperboloid(m)) = acosh(t)*(2/dd)/nyy * m
    float nyy = fmaxf(2.0f * sqrtf(s2) / dd, MINV);
    float sc2 = acoshr(fmaxf(hb0, 1.0f + EPSV)) * (2.0f / dd) / nyy;
    float* Uo = g_u + ((size_t)(h * NV) + i) * 64;
    Uo[l]      = sc2 * m1;
    Uo[l + 32] = sc2 * m2;
}

// ---------------- K4: batched Wo hyp_linear + to_poincare -> g_pc ----------------
// grid (48, 4): block 128, per-lane node
#define PU_OFF  0                      // 128*65 = 8320
#define PW_OFF  8320                   // 64*64  = 4096
#define PO_OFF  12416                  // 4*64*33= 8448
#define PT_OFF  20864                  // 128
#define SMEM_POST ((20864 + 128) * 4)

__global__ __launch_bounds__(128) void k_post1(const float* __restrict__ Wo) {
    extern __shared__ float sm[];
    float*  su  = sm + PU_OFF;
    float*  sW  = sm + PW_OFF;
    float4* sW4 = (float4*)sW;
    float*  st  = sm + PT_OFF;
    int t = threadIdx.x, w = t >> 5, l = t & 31;
    int h = blockIdx.y;
    int nb = blockIdx.x * 128;

    for (int e = t; e < 128 * 64; e += 128) {
        int ln = e >> 6, c = e & 63;
        su[ln * 65 + c] = g_u[((size_t)(h * NV) + nb) * 64 + e];
    }
    for (int e = t; e < 64 * 64; e += 128) {
        int oo = e >> 6, c = e & 63;
        sW[e] = Wo[h * 4225 + (oo + 1) * 65 + 1 + c];
    }
    __syncthreads();

    int ln = w * 32 + l;
    float u[64];
#pragma unroll
    for (int c = 0; c < 64; c++) u[c] = su[ln * 65 + c];

    float* so = sm + PO_OFF + w * 2112;
    float osq = 0.f;
    for (int oo = 0; oo < 64; oo++) {
        float a0 = 0.f, a1 = 0.f, a2 = 0.f, a3 = 0.f;
#pragma unroll
        for (int c4 = 0; c4 < 16; c4++) {
            float4 wv = sW4[oo * 16 + c4];
            a0 += wv.x * u[4 * c4];
            a1 += wv.y * u[4 * c4 + 1];
            a2 += wv.z * u[4 * c4 + 2];
            a3 += wv.w * u[4 * c4 + 3];
        }
        float ov = (a0 + a1) + (a2 + a3);
        so[oo * 33 + l] = ov;
        osq += ov * ov;
    }
    float n2 = fmaxf(sqrtf(osq), MINV);
    float sh = sinhf(n2) / n2;
    float tv = sqrtf(1.0f + sh * sh * osq);
    st[t] = sh / (tv + 1.0f);
    __syncwarp();

    for (int n = 0; n < 32; n++) {
        int nd = nb + w * 32 + n;
        float cn = st[w * 32 + n];
        float* P = g_pc + (size_t)nd * 256 + h * 64;
        P[l]      = cn * so[l * 33 + n];
        P[l + 32] = cn * so[(l + 32) * 33 + n];
    }
}

// ---------------- K5: per-row final logmap scalar ----------------
__global__ __launch_bounds__(256) void k_scal(void) {
    int w = threadIdx.x >> 5, l = threadIdx.x & 31;
    int row = blockIdx.x * 8 + w;
    float q = 0.f;
#pragma unroll
    for (int k = 0; k < 8; k++) {
        float p = g_pc[(size_t)row * 256 + k * 32 + l];
        q += p * p;
    }
    float ssum = wred(q);
    if (l == 0) {
        float dd = fmaxf(1.0f - ssum, MINV);
        float hb0 = (1.0f + ssum) / dd;
        float nyy = fmaxf(2.0f * sqrtf(ssum) / dd, MINV);
        g_s[row] = acoshr(fmaxf(hb0, 1.0f + EPSV)) * (2.0f / dd) / nyy;
    }
}

// ---------------- K6: SGEMM 64x64x16 tiled, scale fused on A load ----------------
__global__ __launch_bounds__(256) void k_lin(void) {
    __shared__ float As[16][68];
    __shared__ float Bs[16][64];
    int t = threadIdx.x;
    int i0 = blockIdx.x * 64, n0 = blockIdx.y * 64;
    int tx = t & 15, ty = t >> 4;
    int lr = t >> 2, lc4 = t & 3;
    int bk = t >> 4, bn4 = t & 15;
    float sr = g_s[i0 + lr];
    float acc[4][4];
#pragma unroll
    for (int i = 0; i < 4; i++)
#pragma unroll
        for (int j = 0; j < 4; j++) acc[i][j] = 0.f;

    for (int k0 = 0; k0 < 256; k0 += 16) {
        __syncthreads();
        float4 av = *(const float4*)&g_pc[(size_t)(i0 + lr) * 256 + k0 + lc4 * 4];
        As[lc4 * 4 + 0][lr] = av.x * sr;
        As[lc4 * 4 + 1][lr] = av.y * sr;
        As[lc4 * 4 + 2][lr] = av.z * sr;
        As[lc4 * 4 + 3][lr] = av.w * sr;
        *(float4*)&Bs[bk][bn4 * 4] =
            *(const float4*)&g_WlP[(size_t)(k0 + bk) * WLN + n0 + bn4 * 4];
        __syncthreads();
#pragma unroll
        for (int k = 0; k < 16; k++) {
            float4 a = *(const float4*)&As[k][ty * 4];
            float4 b = *(const float4*)&Bs[k][tx * 4];
            acc[0][0] += a.x * b.x; acc[0][1] += a.x * b.y; acc[0][2] += a.x * b.z; acc[0][3] += a.x * b.w;
            acc[1][0] += a.y * b.x; acc[1][1] += a.y * b.y; acc[1][2] += a.y * b.z; acc[1][3] += a.y * b.w;
            acc[2][0] += a.z * b.x; acc[2][1] += a.z * b.y; acc[2][2] += a.z * b.z; acc[2][3] += a.z * b.w;
            acc[3][0] += a.w * b.x; acc[3][1] += a.w * b.y; acc[3][2] += a.w * b.z; acc[3][3] += a.w * b.w;
        }
    }
#pragma unroll
    for (int i = 0; i < 4; i++) {
        float4 v = make_float4(acc[i][0], acc[i][1], acc[i][2], acc[i][3]);
        *(float4*)&g_pre[(size_t)(i0 + ty * 4 + i) * WLN + n0 + tx * 4] = v;
    }
}

// ---------------- K7: final expmap0 + hyp_proj ----------------
__global__ __launch_bounds__(256) void k_final(float* __restrict__ out) {
    int w = threadIdx.x >> 5, l = threadIdx.x & 31;
    int row = blockIdx.x * 8 + w;
    float v[8], q = 0.f;
#pragma unroll
    for (int k = 0; k < 8; k++) {
        v[k] = g_pre[(size_t)row * WLN + k * 32 + l];
        if (!(k == 0 && l == 0)) q += v[k] * v[k];
    }
    float t4 = 0.f;
    if (l < 4) { t4 = g_pre[(size_t)row * WLN + 256 + l]; q += t4 * t4; }
    q = wred(q);
    float n2 = fmaxf(sqrtf(q), MINV);
    float sh = sinhf(n2) / n2;
    float tv = sqrtf(1.0f + sh * sh * q);
#pragma unroll
    for (int k = 0; k < 8; k++) {
        float o = (k == 0 && l == 0) ? tv : sh * v[k];
        out[(size_t)row * 260 + k * 32 + l] = o;
    }
    if (l < 4) out[(size_t)row * 260 + 256 + l] = sh * t4;
}

// ---------------- launch ----------------
extern "C" void kernel_launch(void* const* d_in, const int* in_sizes, int n_in,
                              void* d_out, int out_size) {
    const float* x     = (const float*)d_in[0];
    const float* adj   = (const float*)d_in[1];
    const float* W_att = (const float*)d_in[2];
    const float* W_dat = (const float*)d_in[3];
    const float* W_out = (const float*)d_in[4];
    const float* W_lin = (const float*)d_in[5];
    float* out = (float*)d_out;

    cudaFuncSetAttribute(k_feat,  cudaFuncAttributeMaxDynamicSharedMemorySize, SMEM_FEAT);
    cudaFuncSetAttribute(k_post1, cudaFuncAttributeMaxDynamicSharedMemorySize, SMEM_POST);

    k_build<<<dim3(NV / 256, NSEG + 1), 256>>>(adj, W_lin);
    k_feat<<<dim3(NV / 128, 8), 128, SMEM_FEAT>>>(x, W_att, W_dat);
    k_attn<<<NV, 128>>>();
    k_post1<<<dim3(NV / 128, HV), 128, SMEM_POST>>>(W_out);
    k_scal<<<NV / 8, 256>>>();
    k_lin<<<dim3(NV / 64, 5), 256>>>();
    k_final<<<NV / 8, 256>>>(out);
}